// round 10
// baseline (speedup 1.0000x reference)
#include <cuda_runtime.h>
#include <stdint.h>
#include <stdlib.h>

// ---------------------------------------------------------------------------
// GCN 2-layer forward, N=100k, E=1.6M, d=64 — single persistent kernel.
// Phases separated by software grid barriers (all blocks co-resident):
//  0 zero counts, precompute w2r=W2@Wr, c=b2.Wr+br, reset ticket
//  1 degrees (atomics)
//  2 exclusive scan of cnt_in -> row_ptr/cursor (block sums -> serial -> rescan)
//  3 CSR fill {src, rsqrt(1+deg_out[src])}
//  4 per-64-row tiles (dynamic ticket): gather u = rin*(x_self*rout + sum x*sc),
//    y = relu(u@W1+b1), q = rout*(y . w2r)
//  5 out[i] = rin*(q_self + sum_in q) + c
// Indices are int32 (established experimentally in earlier rounds).
// ---------------------------------------------------------------------------

#define MAXN 100352
#define MAXE 1605632
#define D 64
#define FULL 0xffffffffu

__device__ int   g_cnt_out[MAXN];
__device__ int   g_cnt_in[MAXN];
__device__ int   g_row_ptr[MAXN + 1];
__device__ int   g_cursor[MAXN];
__device__ int2  g_csr[MAXE];       // {src, float bits of rsqrt(1+deg_out[src])}
__device__ float g_q[MAXN];
__device__ float g_w2r[D];
__device__ float g_c;
__device__ int   g_blocksum[2048];
__device__ unsigned g_bar_count;
__device__ unsigned g_bar_gen;
__device__ unsigned g_ticket;

__attribute__((constructor))
static void _eager_modules() { setenv("CUDA_MODULE_LOADING", "EAGER", 1); }

// ------------------------- software grid barrier ----------------------------
// Release resets count BEFORE bumping gen, so arrivals for the next barrier
// (only possible after observing the gen bump) never race the reset.
__device__ __forceinline__ void grid_barrier(int nblocks) {
    __syncthreads();
    if (threadIdx.x == 0) {
        __threadfence();
        unsigned gen = *(volatile unsigned*)&g_bar_gen;
        unsigned old = atomicAdd(&g_bar_count, 1u);
        if (old == (unsigned)nblocks - 1u) {
            g_bar_count = 0u;
            __threadfence();
            atomicAdd(&g_bar_gen, 1u);
        } else {
            while (*(volatile unsigned*)&g_bar_gen == gen) __nanosleep(64);
        }
        __threadfence();
    }
    __syncthreads();
}

__device__ __forceinline__ int clampi(int v, int n) {
    return min(max(v, 0), n - 1);
}

// ------------------------------ the kernel ----------------------------------

__global__ __launch_bounds__(256)
void k_all(const float* __restrict__ x,
           const int* __restrict__ src, const int* __restrict__ dst,
           const float* __restrict__ W1, const float* __restrict__ b1,
           const float* __restrict__ W2, const float* __restrict__ b2,
           const float* __restrict__ Wr, const float* __restrict__ br,
           float* __restrict__ out, int n, int e) {
    __shared__ float Ws[D * D];          // 16 KB (phase 4); int alias in phase 2b
    __shared__ float Us[64][D];          // 16 KB (phase 4)
    __shared__ float w2s[D], b1s[D];
    __shared__ int   warp_sums[8];
    __shared__ int   sh_tile;
    __shared__ int   sh_base;

    const int nb   = gridDim.x;
    const int tid  = threadIdx.x;
    const int gtid = blockIdx.x * 256 + tid;
    const int nthr = nb * 256;
    const int lane = tid & 31, wy = tid >> 5;

    // ---- phase 0: zero counts; block 0 precomputes w2r, c, ticket ----
    for (int i = gtid; i < n; i += nthr) { g_cnt_out[i] = 0; g_cnt_in[i] = 0; }
    if (blockIdx.x == 0) {
        if (tid < D) {
            float s = 0.f;
#pragma unroll
            for (int j = 0; j < D; j++) s += W2[tid * D + j] * Wr[j];
            g_w2r[tid] = s;
        }
        if (tid == 0) {
            float c = 0.f;
            for (int j = 0; j < D; j++) c += b2[j] * Wr[j];
            g_c = c + br[0];
            g_ticket = 0u;
        }
    }
    grid_barrier(nb);

    // ---- phase 1: degrees ----
    for (int t = gtid; t < e; t += nthr) {
        atomicAdd(&g_cnt_out[clampi(src[t], n)], 1);
        atomicAdd(&g_cnt_in[clampi(dst[t], n)], 1);
    }
    grid_barrier(nb);

    // ---- phase 2a: per-block chunk sums of cnt_in ----
    const int CH = (n + nb - 1) / nb;
    const int cs = blockIdx.x * CH;
    const int ce = min(n, cs + CH);
    {
        int s = 0;
        for (int i = cs + tid; i < ce; i += 256) s += g_cnt_in[i];
#pragma unroll
        for (int o = 16; o; o >>= 1) s += __shfl_xor_sync(FULL, s, o);
        if (lane == 0) warp_sums[wy] = s;
        __syncthreads();
        if (tid == 0) {
            int t = 0;
            for (int w = 0; w < 8; w++) t += warp_sums[w];
            g_blocksum[blockIdx.x] = t;
        }
    }
    grid_barrier(nb);

    // ---- phase 2b: block 0 serial-scans block sums (nb <= 2048) ----
    if (blockIdx.x == 0) {
        int* sh = (int*)Ws;
        for (int i = tid; i < nb; i += 256) sh[i] = g_blocksum[i];
        __syncthreads();
        if (tid == 0) {
            int run = 0;
            for (int i = 0; i < nb; i++) { int v = sh[i]; sh[i] = run; run += v; }
        }
        __syncthreads();
        for (int i = tid; i < nb; i += 256) g_blocksum[i] = sh[i];
    }
    grid_barrier(nb);

    // ---- phase 2c: rescan chunk, write row_ptr & cursor ----
    {
        if (tid == 0) sh_base = g_blocksum[blockIdx.x];
        __syncthreads();
        int niter = (CH + 255) / 256;
        for (int it = 0; it < niter; it++) {
            int i = cs + it * 256 + tid;
            int v = (i < ce) ? g_cnt_in[i] : 0;
            // block exclusive scan of v
            int s = v;
#pragma unroll
            for (int o = 1; o < 32; o <<= 1) {
                int y = __shfl_up_sync(FULL, s, o);
                if (lane >= o) s += y;
            }
            if (lane == 31) warp_sums[wy] = s;
            __syncthreads();
            if (tid < 8) {
                int w = warp_sums[tid];
#pragma unroll
                for (int o = 1; o < 8; o <<= 1) {
                    int y = __shfl_up_sync(0xffu, w, o);
                    if ((int)tid >= o) w += y;
                }
                warp_sums[tid] = w;
            }
            __syncthreads();
            int base = (wy > 0) ? warp_sums[wy - 1] : 0;
            int excl = sh_base + base + s - v;
            if (i < ce) { g_row_ptr[i] = excl; g_cursor[i] = excl; }
            __syncthreads();
            if (tid == 0) sh_base += warp_sums[7];
            __syncthreads();
        }
        if (gtid == 0) g_row_ptr[n] = e;
    }
    grid_barrier(nb);

    // ---- phase 3: CSR fill ----
    for (int t = gtid; t < e; t += nthr) {
        int s = clampi(src[t], n);
        int d = clampi(dst[t], n);
        float sc = rsqrtf(1.0f + (float)g_cnt_out[s]);
        int pos = atomicAdd(&g_cursor[d], 1);
        g_csr[pos] = make_int2(s, __float_as_int(sc));
    }
    grid_barrier(nb);

    // ---- phase 4: agg + GEMM + q, dynamic tiles of 64 rows ----
#pragma unroll
    for (int i = 0; i < (D * D) / 256; i++)
        Ws[tid + 256 * i] = W1[tid + 256 * i];
    if (tid < D) { w2s[tid] = g_w2r[tid]; b1s[tid] = b1[tid]; }
    __syncthreads();

    const int ntiles = (n + 63) / 64;
    const int half = lane >> 4, cc = lane & 15;
    const float4* x4 = (const float4*)x;

    for (;;) {
        if (tid == 0) sh_tile = (int)atomicAdd(&g_ticket, 1u);
        __syncthreads();
        int tile = sh_tile;
        if (tile >= ntiles) break;
        int row0 = tile * 64;

        for (int r = 0; r < 8; r++) {
            int row = row0 + wy * 8 + r;
            bool valid = row < n;
            int start = 0, end = 0;
            if (valid) { start = g_row_ptr[row]; end = g_row_ptr[row + 1]; }

            float4 a = make_float4(0.f, 0.f, 0.f, 0.f);
            float4 b = make_float4(0.f, 0.f, 0.f, 0.f);

            if (valid && half == 0) {              // self-loop term
                float rt = rsqrtf(1.0f + (float)g_cnt_out[row]);
                float4 v = x4[row * 16 + cc];
                a.x = v.x * rt; a.y = v.y * rt; a.z = v.z * rt; a.w = v.w * rt;
            }
            for (int base = start; base < end; base += 32) {
                int cnt = min(32, end - base);
                int2 my = g_csr[base + min(lane, cnt - 1)];
                int k = 0;
                for (; k + 8 <= cnt; k += 8) {
                    int   s0 = __shfl_sync(FULL, my.x, k + half);
                    float c0 = __int_as_float(__shfl_sync(FULL, my.y, k + half));
                    int   s1 = __shfl_sync(FULL, my.x, k + 2 + half);
                    float c1 = __int_as_float(__shfl_sync(FULL, my.y, k + 2 + half));
                    int   s2 = __shfl_sync(FULL, my.x, k + 4 + half);
                    float c2 = __int_as_float(__shfl_sync(FULL, my.y, k + 4 + half));
                    int   s3 = __shfl_sync(FULL, my.x, k + 6 + half);
                    float c3 = __int_as_float(__shfl_sync(FULL, my.y, k + 6 + half));
                    float4 v0 = x4[s0 * 16 + cc];
                    float4 v1 = x4[s1 * 16 + cc];
                    float4 v2 = x4[s2 * 16 + cc];
                    float4 v3 = x4[s3 * 16 + cc];
                    a.x = fmaf(v0.x, c0, a.x); a.y = fmaf(v0.y, c0, a.y);
                    a.z = fmaf(v0.z, c0, a.z); a.w = fmaf(v0.w, c0, a.w);
                    b.x = fmaf(v1.x, c1, b.x); b.y = fmaf(v1.y, c1, b.y);
                    b.z = fmaf(v1.z, c1, b.z); b.w = fmaf(v1.w, c1, b.w);
                    a.x = fmaf(v2.x, c2, a.x); a.y = fmaf(v2.y, c2, a.y);
                    a.z = fmaf(v2.z, c2, a.z); a.w = fmaf(v2.w, c2, a.w);
                    b.x = fmaf(v3.x, c3, b.x); b.y = fmaf(v3.y, c3, b.y);
                    b.z = fmaf(v3.z, c3, b.z); b.w = fmaf(v3.w, c3, b.w);
                }
                for (; k < cnt; k += 2) {
                    int kk = min(k + half, cnt - 1);
                    int   s0 = __shfl_sync(FULL, my.x, kk);
                    float c0 = __int_as_float(__shfl_sync(FULL, my.y, kk));
                    if (k + half < cnt) {
                        float4 v0 = x4[s0 * 16 + cc];
                        a.x = fmaf(v0.x, c0, a.x); a.y = fmaf(v0.y, c0, a.y);
                        a.z = fmaf(v0.z, c0, a.z); a.w = fmaf(v0.w, c0, a.w);
                    }
                }
            }
            a.x += b.x; a.y += b.y; a.z += b.z; a.w += b.w;
            a.x += __shfl_xor_sync(FULL, a.x, 16);
            a.y += __shfl_xor_sync(FULL, a.y, 16);
            a.z += __shfl_xor_sync(FULL, a.z, 16);
            a.w += __shfl_xor_sync(FULL, a.w, 16);
            if (half == 0) {
                float rin = valid ? rsqrtf(1.0f + (float)g_cnt_in[row]) : 0.f;
                a.x *= rin; a.y *= rin; a.z *= rin; a.w *= rin;
                *(float4*)&Us[wy * 8 + r][cc * 4] = a;
            }
        }
        __syncthreads();

        // GEMM: warp = 8 rows, thread = 8 rows x 2 cols
        float acc[8][2];
#pragma unroll
        for (int r = 0; r < 8; r++) { acc[r][0] = 0.f; acc[r][1] = 0.f; }
#pragma unroll
        for (int k = 0; k < D; k++) {
            float w0 = Ws[k * D + lane];
            float w1 = Ws[k * D + lane + 32];
#pragma unroll
            for (int r = 0; r < 8; r++) {
                float u = Us[wy * 8 + r][k];
                acc[r][0] = fmaf(u, w0, acc[r][0]);
                acc[r][1] = fmaf(u, w1, acc[r][1]);
            }
        }
#pragma unroll
        for (int r = 0; r < 8; r++) {
            int row = row0 + wy * 8 + r;
            float y0 = fmaxf(acc[r][0] + b1s[lane], 0.f);
            float y1 = fmaxf(acc[r][1] + b1s[lane + 32], 0.f);
            float p = y0 * w2s[lane] + y1 * w2s[lane + 32];
#pragma unroll
            for (int o = 16; o; o >>= 1) p += __shfl_xor_sync(FULL, p, o);
            if (lane == 0 && row < n)
                g_q[row] = p * rsqrtf(1.0f + (float)g_cnt_out[row]);
        }
        __syncthreads();   // protect Us before next tile's gather
    }
    grid_barrier(nb);

    // ---- phase 5: out = rin*(q_self + sum_in q) + c  (half-warp per node) ----
    {
        float c = g_c;
        int hw = gtid >> 4;
        int l16 = tid & 15;
        int nhw = nthr >> 4;
        int iters = (n + nhw - 1) / nhw;
        for (int it = 0; it < iters; it++) {
            int node = hw + it * nhw;
            bool v = node < n;
            int start = 0, end = 0;
            if (v) { start = g_row_ptr[node]; end = g_row_ptr[node + 1]; }
            float s = 0.f;
            for (int j = start + l16; j < end; j += 16)
                s += g_q[g_csr[j].x];
#pragma unroll
            for (int o = 8; o; o >>= 1) s += __shfl_xor_sync(FULL, s, o, 16);
            if (v && l16 == 0) {
                float rin = rsqrtf(1.0f + (float)g_cnt_in[node]);
                out[node] = fmaf(s + g_q[node], rin, c);
            }
        }
    }
}

// ------------------------------- launch -------------------------------------

extern "C" void kernel_launch(void* const* d_in, const int* in_sizes, int n_in,
                              void* d_out, int out_size) {
    const float* x   = (const float*)d_in[0];
    const int*   src = (const int*)d_in[1];
    const int*   dst = (const int*)d_in[2];
    const float* W1  = (const float*)d_in[3];
    const float* b1  = (const float*)d_in[4];
    const float* W2  = (const float*)d_in[5];
    const float* b2  = (const float*)d_in[6];
    const float* Wr  = (const float*)d_in[7];
    const float* br  = (const float*)d_in[8];
    float*       out = (float*)d_out;

    const int n = in_sizes[0] / D;
    const int e = in_sizes[1];

    int dev = 0, sms = 0, occ = 0;
    cudaGetDevice(&dev);
    cudaDeviceGetAttribute(&sms, cudaDevAttrMultiProcessorCount, dev);
    cudaOccupancyMaxActiveBlocksPerMultiprocessor(&occ, k_all, 256, 0);
    if (sms < 1) sms = 1;
    if (occ < 1) occ = 1;
    int blocks = sms * occ;
    if (blocks > 2048) blocks = 2048;

    k_all<<<blocks, 256>>>(x, src, dst, W1, b1, W2, b2, Wr, br, out, n, e);
}

// round 11
// speedup vs baseline: 1.1156x; 1.1156x over previous
#include <cuda_runtime.h>
#include <stdint.h>
#include <stdlib.h>

// ---------------------------------------------------------------------------
// GCN 2-layer forward, N=100k, E=1.6M, d=64. Multi-kernel CSR pipeline:
//   zero -> deg -> scan(x3) -> fill {src, rsqrt(1+deg_out[src])} ->
//   fused agg+GEMM+q (occupancy-forced, deep-MLP gather) -> out gather.
// R10 profile: DRAM 2.6%, L2 26%, issue 24%, occ 37% => latency-bound.
// Fix: __launch_bounds__(256,4) (+33% warps) and 8 loads in flight per warp.
// ---------------------------------------------------------------------------

#define MAXN 100352
#define MAXE 1605632
#define D 64
#define FULL 0xffffffffu

__device__ int   g_cnt_out[MAXN];
__device__ int   g_cnt_in[MAXN];
__device__ int   g_row_ptr[MAXN + 1];
__device__ int   g_cursor[MAXN];
__device__ int2  g_csr[MAXE];        // {src, float bits of rsqrt(1+deg_out[src])}
__device__ float g_q[MAXN];
__device__ int   g_partials[1024];

__attribute__((constructor))
static void _eager_modules() { setenv("CUDA_MODULE_LOADING", "EAGER", 1); }

__device__ __forceinline__ int clampi(int v, int n) { return min(max(v, 0), n - 1); }

// ------------------------------ zero ----------------------------------------

__global__ void k_zero(int n) {
    int i = blockIdx.x * 256 + threadIdx.x;
    if (i < n) { g_cnt_out[i] = 0; g_cnt_in[i] = 0; }
}

// ------------------------------- degrees -----------------------------------

__global__ void k_deg(const int* __restrict__ src, const int* __restrict__ dst,
                      int e, int n) {
    int t = blockIdx.x * blockDim.x + threadIdx.x;
    if (t >= e) return;
    atomicAdd(&g_cnt_out[clampi(src[t], n)], 1);
    atomicAdd(&g_cnt_in[clampi(dst[t], n)], 1);
}

// ----------------------- 3-kernel exclusive scan ---------------------------

__global__ void k_scan_partial(int n) {
    __shared__ int sh[256];
    int i = blockIdx.x * 256 + threadIdx.x;
    int v = (i < n) ? g_cnt_in[i] : 0;
    sh[threadIdx.x] = v;
    __syncthreads();
    for (int off = 128; off; off >>= 1) {
        if (threadIdx.x < off) sh[threadIdx.x] += sh[threadIdx.x + off];
        __syncthreads();
    }
    if (threadIdx.x == 0) g_partials[blockIdx.x] = sh[0];
}

__global__ void k_scan_block(int nb) {
    __shared__ int ws[16];
    int t = threadIdx.x, lane = t & 31, wid = t >> 5;
    int v = (t < nb) ? g_partials[t] : 0;
    int s = v;
#pragma unroll
    for (int o = 1; o < 32; o <<= 1) {
        int y = __shfl_up_sync(FULL, s, o);
        if (lane >= o) s += y;
    }
    if (lane == 31) ws[wid] = s;
    __syncthreads();
    if (wid == 0) {
        int w = (lane < 16) ? ws[lane] : 0;
#pragma unroll
        for (int o = 1; o < 16; o <<= 1) {
            int y = __shfl_up_sync(FULL, w, o);
            if (lane >= o) w += y;
        }
        if (lane < 16) ws[lane] = w;
    }
    __syncthreads();
    int base = (wid > 0) ? ws[wid - 1] : 0;
    if (t < nb) g_partials[t] = base + s - v;   // exclusive
}

__global__ void k_scan_final(int n) {
    __shared__ int sh[256];
    int t = threadIdx.x;
    int i = blockIdx.x * 256 + t;
    int v = (i < n) ? g_cnt_in[i] : 0;
    sh[t] = v;
    __syncthreads();
    for (int off = 1; off < 256; off <<= 1) {
        int add = (t >= off) ? sh[t - off] : 0;
        __syncthreads();
        sh[t] += add;
        __syncthreads();
    }
    int excl = sh[t] - v + g_partials[blockIdx.x];
    if (i < n) {
        g_row_ptr[i] = excl;
        g_cursor[i]  = excl;
        if (i == n - 1) g_row_ptr[n] = excl + v;
    }
}

// ------------------------------- CSR fill ----------------------------------

__global__ void k_fill(const int* __restrict__ src, const int* __restrict__ dst,
                       int e, int n) {
    int t = blockIdx.x * blockDim.x + threadIdx.x;
    if (t >= e) return;
    int s = clampi(src[t], n);
    int d = clampi(dst[t], n);
    float sc = rsqrtf(1.0f + (float)g_cnt_out[s]);
    int pos = atomicAdd(&g_cursor[d], 1);
    g_csr[pos] = make_int2(s, __float_as_int(sc));
}

// ---------------- fused aggregation + GEMM + q epilogue --------------------
// Block = 64 rows, 256 threads (8 warps x 8 rows). Half-warp per edge stream,
// 4 edges per half in flight (8 indep 16B loads per warp). Occupancy forced
// to >=4 blocks/SM (<=64 regs) — R10 showed latency-bound at 3 blocks/SM.

__global__ __launch_bounds__(256, 4)
void k_agg_gemm_q(const float* __restrict__ x, const float* __restrict__ W1,
                  const float* __restrict__ b1, const float* __restrict__ W2,
                  const float* __restrict__ Wr, int n) {
    __shared__ float Ws[D * D];      // 16 KB
    __shared__ float Us[64][D];      // 16 KB
    __shared__ float w2s[D], b1s[D];
    const int t = threadIdx.x;

    if (t < D) {
        float s = 0.f;
#pragma unroll
        for (int j = 0; j < D; j++) s += W2[t * D + j] * Wr[j];
        w2s[t] = s;
        b1s[t] = b1[t];
    }
#pragma unroll
    for (int i = 0; i < (D * D) / 256; i++)
        Ws[t + 256 * i] = W1[t + 256 * i];

    const int row0 = blockIdx.x * 64;
    const int wy = t >> 5, lane = t & 31;
    const int half = lane >> 4, cc = lane & 15;
    const float4* x4 = (const float4*)x;

    for (int r = 0; r < 8; r++) {
        int row = row0 + wy * 8 + r;
        bool valid = row < n;
        int start = 0, end = 0;
        if (valid) { start = g_row_ptr[row]; end = g_row_ptr[row + 1]; }

        float4 a = make_float4(0.f, 0.f, 0.f, 0.f);
        float4 b = make_float4(0.f, 0.f, 0.f, 0.f);

        if (valid && half == 0) {                  // self-loop term
            float rt = rsqrtf(1.0f + (float)g_cnt_out[row]);
            float4 v = x4[row * 16 + cc];
            a.x = v.x * rt; a.y = v.y * rt; a.z = v.z * rt; a.w = v.w * rt;
        }

        // halves interleave edges: half h owns j = start+h, start+h+2, ...
        int j = start + half;
        for (; j + 6 < end; j += 8) {              // 4 edges per half in flight
            int2 e0 = g_csr[j];
            int2 e1 = g_csr[j + 2];
            int2 e2 = g_csr[j + 4];
            int2 e3 = g_csr[j + 6];
            float4 v0 = x4[e0.x * 16 + cc];
            float4 v1 = x4[e1.x * 16 + cc];
            float4 v2 = x4[e2.x * 16 + cc];
            float4 v3 = x4[e3.x * 16 + cc];
            float c0 = __int_as_float(e0.y), c1 = __int_as_float(e1.y);
            float c2 = __int_as_float(e2.y), c3 = __int_as_float(e3.y);
            a.x = fmaf(v0.x, c0, a.x); a.y = fmaf(v0.y, c0, a.y);
            a.z = fmaf(v0.z, c0, a.z); a.w = fmaf(v0.w, c0, a.w);
            b.x = fmaf(v1.x, c1, b.x); b.y = fmaf(v1.y, c1, b.y);
            b.z = fmaf(v1.z, c1, b.z); b.w = fmaf(v1.w, c1, b.w);
            a.x = fmaf(v2.x, c2, a.x); a.y = fmaf(v2.y, c2, a.y);
            a.z = fmaf(v2.z, c2, a.z); a.w = fmaf(v2.w, c2, a.w);
            b.x = fmaf(v3.x, c3, b.x); b.y = fmaf(v3.y, c3, b.y);
            b.z = fmaf(v3.z, c3, b.z); b.w = fmaf(v3.w, c3, b.w);
        }
        for (; j < end; j += 2) {
            int2 e0 = g_csr[j];
            float c0 = __int_as_float(e0.y);
            float4 v0 = x4[e0.x * 16 + cc];
            a.x = fmaf(v0.x, c0, a.x); a.y = fmaf(v0.y, c0, a.y);
            a.z = fmaf(v0.z, c0, a.z); a.w = fmaf(v0.w, c0, a.w);
        }
        a.x += b.x; a.y += b.y; a.z += b.z; a.w += b.w;
        // combine halves
        a.x += __shfl_xor_sync(FULL, a.x, 16);
        a.y += __shfl_xor_sync(FULL, a.y, 16);
        a.z += __shfl_xor_sync(FULL, a.z, 16);
        a.w += __shfl_xor_sync(FULL, a.w, 16);
        if (half == 0) {
            float rin = valid ? rsqrtf(1.0f + (float)g_cnt_in[row]) : 0.f;
            a.x *= rin; a.y *= rin; a.z *= rin; a.w *= rin;
            *(float4*)&Us[wy * 8 + r][cc * 4] = a;
        }
    }
    __syncthreads();

    // GEMM: thread = 8 rows x 2 cols
    float acc[8][2];
#pragma unroll
    for (int r = 0; r < 8; r++) { acc[r][0] = 0.f; acc[r][1] = 0.f; }
#pragma unroll
    for (int k = 0; k < D; k++) {
        float w0 = Ws[k * D + lane];
        float w1 = Ws[k * D + lane + 32];
#pragma unroll
        for (int r = 0; r < 8; r++) {
            float u = Us[wy * 8 + r][k];           // warp broadcast
            acc[r][0] = fmaf(u, w0, acc[r][0]);
            acc[r][1] = fmaf(u, w1, acc[r][1]);
        }
    }
#pragma unroll
    for (int r = 0; r < 8; r++) {
        int row = row0 + wy * 8 + r;
        float y0 = fmaxf(acc[r][0] + b1s[lane], 0.f);
        float y1 = fmaxf(acc[r][1] + b1s[lane + 32], 0.f);
        float p = y0 * w2s[lane] + y1 * w2s[lane + 32];
#pragma unroll
        for (int o = 16; o; o >>= 1) p += __shfl_xor_sync(FULL, p, o);
        if (lane == 0 && row < n)
            g_q[row] = p * rsqrtf(1.0f + (float)g_cnt_out[row]);
    }
}

// -------------------- layer-2 gather + finalize (fused) ---------------------

__global__ void k_out(const float* __restrict__ b2, const float* __restrict__ Wr,
                      const float* __restrict__ br, float* __restrict__ out, int n) {
    __shared__ float c_sh;
    if (threadIdx.x == 0) {
        float c = 0.f;
        for (int j = 0; j < D; j++) c += b2[j] * Wr[j];
        c_sh = c + br[0];
    }
    __syncthreads();
    int node = (blockIdx.x * blockDim.x + threadIdx.x) >> 4;
    int lane = threadIdx.x & 15;
    if (node >= n) return;
    int start = g_row_ptr[node], end = g_row_ptr[node + 1];
    float s = 0.f;
    for (int j = start + lane; j < end; j += 16)
        s += g_q[g_csr[j].x];
#pragma unroll
    for (int o = 8; o; o >>= 1) s += __shfl_xor_sync(FULL, s, o, 16);
    if (lane == 0) {
        float rin = rsqrtf(1.0f + (float)g_cnt_in[node]);
        out[node] = fmaf(s + g_q[node], rin, c_sh);
    }
}

// ------------------------------- launch -------------------------------------

extern "C" void kernel_launch(void* const* d_in, const int* in_sizes, int n_in,
                              void* d_out, int out_size) {
    const float* x   = (const float*)d_in[0];
    const int*   src = (const int*)d_in[1];
    const int*   dst = (const int*)d_in[2];
    const float* W1  = (const float*)d_in[3];
    const float* b1  = (const float*)d_in[4];
    const float* W2  = (const float*)d_in[5];
    const float* b2  = (const float*)d_in[6];
    const float* Wr  = (const float*)d_in[7];
    const float* br  = (const float*)d_in[8];
    float*       out = (float*)d_out;

    const int n = in_sizes[0] / D;
    const int e = in_sizes[1];
    const int nb = (n + 255) / 256;

    k_zero<<<nb, 256>>>(n);
    k_deg<<<(e + 255) / 256, 256>>>(src, dst, e, n);
    k_scan_partial<<<nb, 256>>>(n);
    k_scan_block<<<1, 512>>>(nb);
    k_scan_final<<<nb, 256>>>(n);
    k_fill<<<(e + 255) / 256, 256>>>(src, dst, e, n);

    k_agg_gemm_q<<<(n + 63) / 64, 256>>>(x, W1, b1, W2, Wr, n);
    k_out<<<((n * 16) + 255) / 256, 256>>>(b2, Wr, br, out, n);
}

// round 12
// speedup vs baseline: 1.1330x; 1.0156x over previous
#include <cuda_runtime.h>
#include <cuda_fp16.h>
#include <stdint.h>
#include <stdlib.h>

// ---------------------------------------------------------------------------
// GCN 2-layer forward, N=100k, E=1.6M, d=64.
// Pipeline (6 launches; agg at index 3 = the ncu-captured slot):
//  0 k_deg        degrees via atomics (cnt arrays are zero: module-load init
//                 on call 1, trailing k_reset on every later call)
//  1 k_scan_stage single-pass decoupled-lookback scan of cnt_in -> row_ptr,
//                 cursor; surplus blocks stage h = x*rsqrt(1+deg_out) as fp16
//  2 k_fill       CSR fill (int src only; scale folded into staged h)
//  3 k_agg_gemm_q per 64-row tile: u = rin*(h_self + sum h[src]) (fp16 reads,
//                 fp32 accum), y = relu(u@W1+b1), q = rout*(y . W2@Wr)
//  4 k_out        out = rin*(q_self + sum_in q) + (b2.Wr + br)
//  5 k_reset      re-zero cnt/desc/ticket for the next replay
// ---------------------------------------------------------------------------

#define MAXN 100352
#define MAXE 1605632
#define D 64
#define FULL 0xffffffffu
#define SCAN_TILE 1024
#define MAX_TILES ((MAXN + SCAN_TILE - 1) / SCAN_TILE)

__device__ int   g_cnt_out[MAXN];
__device__ int   g_cnt_in[MAXN];
__device__ int   g_row_ptr[MAXN + 1];
__device__ int   g_cursor[MAXN];
__device__ int   g_csr[MAXE];              // src only (4 B/edge)
__device__ __half2 g_h[MAXN * D / 2];      // staged h = x*rout, fp16 (12.8 MB)
__device__ float g_q[MAXN];
__device__ unsigned long long g_desc[MAX_TILES];  // lookback: status<<32 | value
__device__ unsigned g_scan_ticket;

__attribute__((constructor))
static void _eager_modules() { setenv("CUDA_MODULE_LOADING", "EAGER", 1); }

__device__ __forceinline__ int clampi(int v, int n) { return min(max(v, 0), n - 1); }

// ------------------------------- degrees -----------------------------------

__global__ void k_deg(const int* __restrict__ src, const int* __restrict__ dst,
                      int e, int n) {
    int t = blockIdx.x * blockDim.x + threadIdx.x;
    if (t >= e) return;
    atomicAdd(&g_cnt_out[clampi(src[t], n)], 1);
    atomicAdd(&g_cnt_in[clampi(dst[t], n)], 1);
}

// -------------- single-pass scan (decoupled lookback) + fp16 staging --------
// Blocks [0, ntiles): scan tiles of 1024 (ticket-ordered => no deadlock).
// Blocks [ntiles, ...): stage h[i] = x[i] * rsqrt(1+deg_out(row)) as fp16.

__global__ void k_scan_stage(const float* __restrict__ x, int n, int ntiles) {
    if ((int)blockIdx.x >= ntiles) {
        int idx = (blockIdx.x - ntiles) * 256 + threadIdx.x;   // float4 index
        if (idx < n * (D / 4)) {
            int row = idx >> 4;
            float rt = rsqrtf(1.0f + (float)g_cnt_out[row]);
            float4 v = ((const float4*)x)[idx];
            ((__half2*)g_h)[idx * 2]     = __floats2half2_rn(v.x * rt, v.y * rt);
            ((__half2*)g_h)[idx * 2 + 1] = __floats2half2_rn(v.z * rt, v.w * rt);
        }
        return;
    }

    __shared__ int sh_tile, sh_prefix;
    __shared__ int warp_agg[8];
    const int t = threadIdx.x, lane = t & 31, wy = t >> 5;

    if (t == 0) sh_tile = (int)atomicAdd(&g_scan_ticket, 1u);
    __syncthreads();
    const int tile = sh_tile;
    const int base = tile * SCAN_TILE;

    // load 4 elements per thread
    int i0 = base + t * 4;
    int4 v = make_int4(0, 0, 0, 0);
    if (i0 + 3 < n) v = *(const int4*)&g_cnt_in[i0];
    else {
        if (i0     < n) v.x = g_cnt_in[i0];
        if (i0 + 1 < n) v.y = g_cnt_in[i0 + 1];
        if (i0 + 2 < n) v.z = g_cnt_in[i0 + 2];
        if (i0 + 3 < n) v.w = g_cnt_in[i0 + 3];
    }
    int tsum = v.x + v.y + v.z + v.w;

    // warp inclusive scan of tsum
    int sc = tsum;
#pragma unroll
    for (int o = 1; o < 32; o <<= 1) {
        int y = __shfl_up_sync(FULL, sc, o);
        if (lane >= o) sc += y;
    }
    if (lane == 31) warp_agg[wy] = sc;
    __syncthreads();
    if (t < 8) {
        int w = warp_agg[t];
#pragma unroll
        for (int o = 1; o < 8; o <<= 1) {
            int y = __shfl_up_sync(0xffu, w, o);
            if (t >= o) w += y;
        }
        warp_agg[t] = w;      // inclusive warp-total scan
    }
    __syncthreads();
    const int blk_total = warp_agg[7];
    const int texcl = ((wy > 0) ? warp_agg[wy - 1] : 0) + sc - tsum;

    // publish aggregate, look back for prefix (thread 0)
    if (t == 0) {
        if (tile == 0) {
            atomicExch(&g_desc[0], (2ULL << 32) | (unsigned)blk_total);
            sh_prefix = 0;
        } else {
            atomicExch(&g_desc[tile], (1ULL << 32) | (unsigned)blk_total);
            int pfx = 0;
            for (int k = tile - 1; k >= 0; k--) {
                unsigned long long d;
                do {
                    d = atomicAdd(&g_desc[k], 0ULL);
                    if ((d >> 32) == 0ULL) __nanosleep(40);
                } while ((d >> 32) == 0ULL);
                pfx += (int)(unsigned)d;
                if ((d >> 32) == 2ULL) break;
            }
            atomicExch(&g_desc[tile], (2ULL << 32) | (unsigned)(pfx + blk_total));
            sh_prefix = pfx;
        }
    }
    __syncthreads();

    int e0 = sh_prefix + texcl;
    int e1 = e0 + v.x, e2 = e1 + v.y, e3 = e2 + v.z;
    if (i0     < n) { g_row_ptr[i0]     = e0; g_cursor[i0]     = e0; }
    if (i0 + 1 < n) { g_row_ptr[i0 + 1] = e1; g_cursor[i0 + 1] = e1; }
    if (i0 + 2 < n) { g_row_ptr[i0 + 2] = e2; g_cursor[i0 + 2] = e2; }
    if (i0 + 3 < n) { g_row_ptr[i0 + 3] = e3; g_cursor[i0 + 3] = e3; }
    if (i0     == n - 1) g_row_ptr[n] = e1;
    if (i0 + 1 == n - 1) g_row_ptr[n] = e2;
    if (i0 + 2 == n - 1) g_row_ptr[n] = e3;
    if (i0 + 3 == n - 1) g_row_ptr[n] = e3 + v.w;
}

// ------------------------------- CSR fill ----------------------------------

__global__ void k_fill(const int* __restrict__ src, const int* __restrict__ dst,
                       int e, int n) {
    int t = blockIdx.x * blockDim.x + threadIdx.x;
    if (t >= e) return;
    int s = clampi(src[t], n);
    int d = clampi(dst[t], n);
    int pos = atomicAdd(&g_cursor[d], 1);
    g_csr[pos] = s;
}

// ---------------- fused aggregation + GEMM + q epilogue --------------------
// Block = 64 rows, 256 threads (8 warps x 8 rows). Half-warp per edge stream,
// lane cc covers 4 features (8 B fp16). 128 B per edge = 1 L1 line.

__device__ __forceinline__ void acc_h(float4& a, uint2 hv) {
    float2 f0 = __half22float2(*(__half2*)&hv.x);
    float2 f1 = __half22float2(*(__half2*)&hv.y);
    a.x += f0.x; a.y += f0.y; a.z += f1.x; a.w += f1.y;
}

__global__ __launch_bounds__(256, 4)
void k_agg_gemm_q(const float* __restrict__ W1, const float* __restrict__ b1,
                  const float* __restrict__ W2, const float* __restrict__ Wr,
                  int n) {
    __shared__ float Ws[D * D];
    __shared__ float Us[64][D];
    __shared__ float w2s[D], b1s[D];
    const int t = threadIdx.x;

    if (t < D) {
        float s = 0.f;
#pragma unroll
        for (int j = 0; j < D; j++) s += W2[t * D + j] * Wr[j];
        w2s[t] = s;
        b1s[t] = b1[t];
    }
#pragma unroll
    for (int i = 0; i < (D * D) / 256; i++)
        Ws[t + 256 * i] = W1[t + 256 * i];

    const int row0 = blockIdx.x * 64;
    const int wy = t >> 5, lane = t & 31;
    const int half = lane >> 4, cc = lane & 15;
    const uint2* h2 = (const uint2*)g_h;    // row stride = 16 uint2 (128 B)

    for (int r = 0; r < 8; r++) {
        int row = row0 + wy * 8 + r;
        bool valid = row < n;
        int start = 0, end = 0;
        if (valid) { start = g_row_ptr[row]; end = g_row_ptr[row + 1]; }

        float4 a = make_float4(0.f, 0.f, 0.f, 0.f);
        float4 b = make_float4(0.f, 0.f, 0.f, 0.f);

        if (valid && half == 0)                     // self term (staged h)
            acc_h(a, h2[row * 16 + cc]);

        int j = start + half;                        // halves interleave edges
        for (; j + 6 < end; j += 8) {                // 4 edges/half in flight
            int s0 = g_csr[j], s1 = g_csr[j + 2], s2 = g_csr[j + 4], s3 = g_csr[j + 6];
            uint2 q0 = h2[s0 * 16 + cc];
            uint2 q1 = h2[s1 * 16 + cc];
            uint2 q2 = h2[s2 * 16 + cc];
            uint2 q3 = h2[s3 * 16 + cc];
            acc_h(a, q0); acc_h(b, q1); acc_h(a, q2); acc_h(b, q3);
        }
        for (; j < end; j += 2)
            acc_h(a, h2[g_csr[j] * 16 + cc]);

        a.x += b.x; a.y += b.y; a.z += b.z; a.w += b.w;
        a.x += __shfl_xor_sync(FULL, a.x, 16);
        a.y += __shfl_xor_sync(FULL, a.y, 16);
        a.z += __shfl_xor_sync(FULL, a.z, 16);
        a.w += __shfl_xor_sync(FULL, a.w, 16);
        if (half == 0) {
            float rin = valid ? rsqrtf(1.0f + (float)g_cnt_in[row]) : 0.f;
            a.x *= rin; a.y *= rin; a.z *= rin; a.w *= rin;
            *(float4*)&Us[wy * 8 + r][cc * 4] = a;
        }
    }
    __syncthreads();

    // GEMM: thread = 8 rows x 2 cols
    float acc[8][2];
#pragma unroll
    for (int r = 0; r < 8; r++) { acc[r][0] = 0.f; acc[r][1] = 0.f; }
#pragma unroll
    for (int k = 0; k < D; k++) {
        float w0 = Ws[k * D + lane];
        float w1 = Ws[k * D + lane + 32];
#pragma unroll
        for (int r = 0; r < 8; r++) {
            float u = Us[wy * 8 + r][k];
            acc[r][0] = fmaf(u, w0, acc[r][0]);
            acc[r][1] = fmaf(u, w1, acc[r][1]);
        }
    }
#pragma unroll
    for (int r = 0; r < 8; r++) {
        int row = row0 + wy * 8 + r;
        float y0 = fmaxf(acc[r][0] + b1s[lane], 0.f);
        float y1 = fmaxf(acc[r][1] + b1s[lane + 32], 0.f);
        float p = y0 * w2s[lane] + y1 * w2s[lane + 32];
#pragma unroll
        for (int o = 16; o; o >>= 1) p += __shfl_xor_sync(FULL, p, o);
        if (lane == 0 && row < n)
            g_q[row] = p * rsqrtf(1.0f + (float)g_cnt_out[row]);
    }
}

// -------------------- layer-2 gather + finalize (fused) ---------------------

__global__ void k_out(const float* __restrict__ b2, const float* __restrict__ Wr,
                      const float* __restrict__ br, float* __restrict__ out, int n) {
    __shared__ float c_sh;
    if (threadIdx.x == 0) {
        float c = 0.f;
        for (int j = 0; j < D; j++) c += b2[j] * Wr[j];
        c_sh = c + br[0];
    }
    __syncthreads();
    int node = (blockIdx.x * blockDim.x + threadIdx.x) >> 4;
    int lane = threadIdx.x & 15;
    if (node >= n) return;
    int start = g_row_ptr[node], end = g_row_ptr[node + 1];
    float s = 0.f;
    for (int j = start + lane; j < end; j += 16)
        s += g_q[g_csr[j]];
#pragma unroll
    for (int o = 8; o; o >>= 1) s += __shfl_xor_sync(FULL, s, o, 16);
    if (lane == 0) {
        float rin = rsqrtf(1.0f + (float)g_cnt_in[node]);
        out[node] = fmaf(s + g_q[node], rin, c_sh);
    }
}

// -------------------------- trailing state reset ----------------------------
// Restores the zeroed-state invariant for the next (graph-replayed) call.

__global__ void k_reset(int n, int ntiles) {
    int i = blockIdx.x * 256 + threadIdx.x;
    if (i < n) { g_cnt_out[i] = 0; g_cnt_in[i] = 0; }
    if (i < ntiles) g_desc[i] = 0ULL;
    if (i == 0) g_scan_ticket = 0u;
}

// ------------------------------- launch -------------------------------------

extern "C" void kernel_launch(void* const* d_in, const int* in_sizes, int n_in,
                              void* d_out, int out_size) {
    const float* x   = (const float*)d_in[0];
    const int*   src = (const int*)d_in[1];
    const int*   dst = (const int*)d_in[2];
    const float* W1  = (const float*)d_in[3];
    const float* b1  = (const float*)d_in[4];
    const float* W2  = (const float*)d_in[5];
    const float* b2  = (const float*)d_in[6];
    const float* Wr  = (const float*)d_in[7];
    const float* br  = (const float*)d_in[8];
    float*       out = (float*)d_out;

    const int n = in_sizes[0] / D;
    const int e = in_sizes[1];
    const int ntiles = (n + SCAN_TILE - 1) / SCAN_TILE;
    const int stage_blocks = (n * (D / 4) + 255) / 256;

    k_deg<<<(e + 255) / 256, 256>>>(src, dst, e, n);                 // 0
    k_scan_stage<<<ntiles + stage_blocks, 256>>>(x, n, ntiles);      // 1
    k_fill<<<(e + 255) / 256, 256>>>(src, dst, e, n);                // 2
    k_agg_gemm_q<<<(n + 63) / 64, 256>>>(W1, b1, W2, Wr, n);         // 3 (ncu)
    k_out<<<((n * 16) + 255) / 256, 256>>>(b2, Wr, br, out, n);      // 4
    k_reset<<<(n + 255) / 256, 256>>>(n, ntiles);                    // 5
}